// round 15
// baseline (speedup 1.0000x reference)
#include <cuda_runtime.h>
#include <cuda_fp16.h>
#include <cstdint>

// Problem constants
#define CCH 256
#define HH 336
#define WW 336
#define NROI 2000
#define POOLP 7
#define K1 (CCH * POOLP * POOLP)  // 12544
#define FF 256

// ---- integral image segmentation ----
#define NSEG 14
#define SEGH 24              // 14 * 24 = 336

// ---- GEMM1 (1-term, BK=64, 4-stage, single-barrier, always-commit) ----
#define KSP 9                  // split-K slices for GEMM1 -> 144 CTAs
#define NCH64 (K1 / 64)        // 196 BK-64 chunks total
#define Q64 (NCH64 / KSP)      // 21
#define R64 (NCH64 % KSP)      // 7
#define ROWB1 144              // 128B data + 16B pad
#define G1_A 0
#define G1_BH 18432            // 128*144
#define G1_STAGE 55296         // + 256*144
#define NST1 4
// ---- GEMM2 (BK=32, split-K=8 -> 128 CTAs, nchk=1) ----
#define KSP2 8
#define SLICE2 (FF / KSP2)     // 32
#define NCHK2 (SLICE2 / 32)    // 1
#define ROWB 80
#define NSTAGE 3

// ---------------- static device scratch ----------------
__device__ float g_colsum[(size_t)NSEG * CCH * WW];            // [s][c][x]
__device__ float g_P[(size_t)NSEG * (WW + 1) * CCH];           // [s][x][c]
__device__ float g_ii[(size_t)(HH + 1) * (WW + 1) * CCH];      // [y][x][c]
__device__ __half g_Ahf[(size_t)NROI * K1];
__device__ __half g_Bhi[(size_t)FF * K1];
__device__ float g_part1[(size_t)KSP * NROI * FF];
__device__ __half g_h1hi[(size_t)NROI * FF];
__device__ __half g_h1lo[(size_t)NROI * FF];
__device__ __half g_B2hi[(size_t)FF * FF];
__device__ __half g_B2lo[(size_t)FF * FF];
__device__ float g_part2[(size_t)KSP2 * NROI * FF];

// ================= helpers =================
__device__ __forceinline__ uint32_t smem_u32(const void* p) {
    uint32_t a;
    asm("{ .reg .u64 t; cvta.to.shared.u64 t, %1; cvt.u32.u64 %0, t; }" : "=r"(a) : "l"(p));
    return a;
}
#define CPA16(sdst, gsrc) \
    asm volatile("cp.async.cg.shared.global [%0], [%1], 16;" \
                 :: "r"(sdst), "l"(__cvta_generic_to_global(gsrc)) : "memory")
#define CPA_COMMIT() asm volatile("cp.async.commit_group;" ::: "memory")
#define CPA_WAIT0()  asm volatile("cp.async.wait_group 0;" ::: "memory")
#define CPA_WAIT2()  asm volatile("cp.async.wait_group 2;" ::: "memory")

#define LDSM4(r0, r1, r2, r3, addr) \
    asm volatile("ldmatrix.sync.aligned.m8n8.x4.shared.b16 {%0,%1,%2,%3}, [%4];" \
                 : "=r"(r0), "=r"(r1), "=r"(r2), "=r"(r3) : "r"(addr))

__device__ __forceinline__ void mma16816(float* c, const uint32_t* a,
                                         uint32_t b0, uint32_t b1) {
    asm volatile(
        "mma.sync.aligned.m16n8k16.row.col.f32.f16.f16.f32 "
        "{%0,%1,%2,%3}, {%4,%5,%6,%7}, {%8,%9}, {%0,%1,%2,%3};"
        : "+f"(c[0]), "+f"(c[1]), "+f"(c[2]), "+f"(c[3])
        : "r"(a[0]), "r"(a[1]), "r"(a[2]), "r"(a[3]), "r"(b0), "r"(b1));
}

// warp-inclusive scan of one 336-value row held as 11 chunks (x = chunk*32+lane)
__device__ __forceinline__ void warp_row_scan(float* v, int lane) {
    float carry = 0.f;
#pragma unroll
    for (int chunk = 0; chunk < 11; chunk++) {
        float x = v[chunk];
#pragma unroll
        for (int off = 1; off < 32; off <<= 1) {
            float t = __shfl_up_sync(0xffffffffu, x, off);
            if (lane >= off) x += t;
        }
        float tot = __shfl_sync(0xffffffffu, x, 31);
        x += carry;
        carry += tot;
        v[chunk] = x;
    }
}

// ---------------- kernel 1a: per-segment column sums of raw features ---------
// grid (NSEG, CCH), 336 threads. colsum[s][c][x] = sum_{y in seg} f[c][y][x]
__global__ void k_colsum(const float* __restrict__ f) {
    int s = blockIdx.x, c = blockIdx.y, x = threadIdx.x;
    const float* base = f + (size_t)c * HH * WW + (size_t)s * SEGH * WW + x;
    float acc = 0.f;
#pragma unroll
    for (int i = 0; i < SEGH; i++) acc += base[i * WW];
    g_colsum[((size_t)s * CCH + c) * WW + x] = acc;
}

// ---------------- kernel 1b: segment-start prefixes P[s][x][c] ---------------
// grid (NSEG, CCH/32), 1024 threads (32 warps; warp = channel).
// P[s][x][c] = xscan( sum_{s'<s} colsum[s'][c] )[x]  (P[s][0][c] = 0)
__global__ void k_segprefix() {
    __shared__ float sP[32][WW + 1];
    int s = blockIdx.x, cg = blockIdx.y;
    int w = threadIdx.x >> 5, lane = threadIdx.x & 31;
    int c = cg * 32 + w;
    float v[11];
#pragma unroll
    for (int chunk = 0; chunk < 11; chunk++) v[chunk] = 0.f;
    for (int sp = 0; sp < s; sp++) {
        const float* row = &g_colsum[((size_t)sp * CCH + c) * WW];
#pragma unroll
        for (int chunk = 0; chunk < 11; chunk++) {
            int x = chunk * 32 + lane;
            if (x < WW) v[chunk] += row[x];
        }
    }
    warp_row_scan(v, lane);
    if (lane == 0) sP[w][0] = 0.f;
#pragma unroll
    for (int chunk = 0; chunk < 11; chunk++) {
        int x = chunk * 32 + lane;
        if (x < WW) sP[w][x + 1] = v[chunk];
    }
    __syncthreads();
    size_t base = (size_t)s * (WW + 1) * CCH + cg * 32;
    for (int i = threadIdx.x; i < (WW + 1) * 32; i += 1024) {
        int x = i >> 5, cl = i & 31;
        g_P[base + (size_t)x * CCH + cl] = sP[cl][x];
    }
}

// ---------------- kernel 1c: fused x-scan + y-accumulate -> ii ---------------
// grid (NSEG, CCH/32), 1024 threads (warp = channel). Block s writes ii rows
// 24s+1 .. 24s+24; block s=0 also writes the zero row ii[0].
__global__ void k_iscan(const float* __restrict__ f) {
    __shared__ float sB[32][WW + 1];
    int s = blockIdx.x, cg = blockIdx.y;
    int w = threadIdx.x >> 5, lane = threadIdx.x & 31;
    int c = cg * 32 + w;
    const size_t rowstride = (size_t)(WW + 1) * CCH;

    // zero row (block s == 0)
    if (s == 0) {
        size_t b0 = (size_t)cg * 32;
        for (int i = threadIdx.x; i < (WW + 1) * 32; i += 1024) {
            int x = i >> 5, cl = i & 31;
            g_ii[b0 + (size_t)x * CCH + cl] = 0.f;
        }
    }

    // stage P[s] into smem (coalesced), then init per-lane running rows
    {
        size_t pb = (size_t)s * (WW + 1) * CCH + cg * 32;
        for (int i = threadIdx.x; i < (WW + 1) * 32; i += 1024) {
            int x = i >> 5, cl = i & 31;
            sB[cl][x] = g_P[pb + (size_t)x * CCH + cl];
        }
    }
    __syncthreads();
    float runrow[11];
#pragma unroll
    for (int chunk = 0; chunk < 11; chunk++) {
        int xo = chunk * 32 + lane + 1;
        runrow[chunk] = (xo <= WW) ? sB[w][xo] : 0.f;
    }
    __syncthreads();

    const float* frow = f + (size_t)c * HH * WW + (size_t)s * SEGH * WW;
    for (int y = 0; y < SEGH; y++) {
        float v[11];
#pragma unroll
        for (int chunk = 0; chunk < 11; chunk++) {
            int x = chunk * 32 + lane;
            v[chunk] = (x < WW) ? frow[y * WW + x] : 0.f;
        }
        warp_row_scan(v, lane);
        if (lane == 0) sB[w][0] = 0.f;
#pragma unroll
        for (int chunk = 0; chunk < 11; chunk++) {
            int x = chunk * 32 + lane;
            runrow[chunk] += v[chunk];
            if (x < WW) sB[w][x + 1] = runrow[chunk];
        }
        __syncthreads();
        size_t base = (size_t)(s * SEGH + y + 1) * rowstride + cg * 32;
        for (int i = threadIdx.x; i < (WW + 1) * 32; i += 1024) {
            int x = i >> 5, cl = i & 31;
            g_ii[base + (size_t)x * CCH + cl] = sB[cl][x];
        }
        __syncthreads();
    }
}

// ---------------- kernel 3: ROI pool -> fp16 A ------------------------------
__global__ void k_pool(const int* __restrict__ rois) {
    int roi = blockIdx.x, c = threadIdx.x;
    int x1 = rois[roi * 4 + 0], y1 = rois[roi * 4 + 1];
    int x2 = rois[roi * 4 + 2], y2 = rois[roi * 4 + 3];
    int Ly = y2 - y1 + 1, Lx = x2 - x1 + 1;
    const size_t rowstride = (size_t)(WW + 1) * CCH;
    size_t outbase = (size_t)roi * K1 + c;
#pragma unroll
    for (int p = 0; p < POOLP * POOLP; p++) {
        int py = p / POOLP, px = p % POOLP;
        int ylo = y1 + (py * Ly) / POOLP;
        int yhi = y1 + ((py + 1) * Ly + POOLP - 1) / POOLP;
        int xlo = x1 + (px * Lx) / POOLP;
        int xhi = x1 + ((px + 1) * Lx + POOLP - 1) / POOLP;
        float s = g_ii[(size_t)yhi * rowstride + (size_t)xhi * CCH + c]
                - g_ii[(size_t)ylo * rowstride + (size_t)xhi * CCH + c]
                - g_ii[(size_t)yhi * rowstride + (size_t)xlo * CCH + c]
                + g_ii[(size_t)ylo * rowstride + (size_t)xlo * CCH + c];
        float v = s * (1.f / (float)((yhi - ylo) * (xhi - xlo)));
        g_Ahf[outbase + (size_t)p * CCH] = __float2half_rn(v);
    }
}

// ---------------- kernel 4: w1 -> transposed fp16 [f][p*256+c] ---------------
__global__ void k_prep_w1(const float* __restrict__ w1) {
    __shared__ float s[32][33];
    int p = blockIdx.x, c0 = blockIdx.y * 32, f0 = blockIdx.z * 32;
    int tx = threadIdx.x, ty = threadIdx.y;
#pragma unroll
    for (int i = 0; i < 4; i++) {
        int cl = ty + i * 8;
        s[cl][tx] = w1[((size_t)(c0 + cl) * (POOLP * POOLP) + p) * FF + f0 + tx];
    }
    __syncthreads();
#pragma unroll
    for (int i = 0; i < 4; i++) {
        int fl = ty + i * 8;
        size_t idx = (size_t)(f0 + fl) * K1 + (size_t)p * CCH + c0 + tx;
        g_Bhi[idx] = __float2half_rn(s[tx][fl]);
    }
}

// ---------------- kernel 4b: w2 -> transposed fp16 hi/lo [f][k] --------------
__global__ void k_prep_w2(const float* __restrict__ w2) {
    __shared__ float s[32][33];
    int k0 = blockIdx.x * 32, f0 = blockIdx.y * 32;
    int tx = threadIdx.x, ty = threadIdx.y;
#pragma unroll
    for (int i = 0; i < 4; i++) {
        int kl = ty + i * 8;
        s[kl][tx] = w2[(size_t)(k0 + kl) * FF + f0 + tx];
    }
    __syncthreads();
#pragma unroll
    for (int i = 0; i < 4; i++) {
        int fl = ty + i * 8;
        float v = s[tx][fl];
        __half hi = __float2half_rn(v);
        __half lo = __float2half_rn(v - __half2float(hi));
        size_t idx = (size_t)(f0 + fl) * FF + k0 + tx;
        g_B2hi[idx] = hi;
        g_B2lo[idx] = lo;
    }
}

// ---------------- kernel 5a: GEMM1 HMMA (1-term, BK=64, 4-stage) -------------
__global__ __launch_bounds__(512) void k_hmma1(
    const __half* __restrict__ A, const __half* __restrict__ Bhi,
    float* __restrict__ Cpart) {
    extern __shared__ char sm[];
    const uint32_t smb = smem_u32(sm);
    const int tid = threadIdx.x;
    const int wid = tid >> 5, lane = tid & 31;
    const int m0 = blockIdx.x * 128;
    const int z = blockIdx.z;
    const int nchk = (z < R64) ? (Q64 + 1) : Q64;
    const int cstart = z * Q64 + min(z, R64);
    const size_t kbase = (size_t)cstart * 64;

    const int warpM = (wid >> 2) * 32;
    const int warpN = (wid & 3) * 64;

    const int lr = tid >> 2;
    const int seg = tid & 3;
    int garow = m0 + lr;
    if (garow >= NROI) garow = NROI - 1;
    const __half* gA = A + (size_t)garow * K1 + seg * 16;
    const __half* gB0h = Bhi + (size_t)lr * K1 + seg * 16;
    const __half* gB1h = Bhi + (size_t)(lr + 128) * K1 + seg * 16;
    const uint32_t aoff = (uint32_t)lr * ROWB1 + seg * 32;
    const uint32_t boff0 = aoff;
    const uint32_t boff1 = (uint32_t)(lr + 128) * ROWB1 + seg * 32;

    float acc[2][8][4];
#pragma unroll
    for (int mi = 0; mi < 2; mi++)
#pragma unroll
        for (int nf = 0; nf < 8; nf++)
#pragma unroll
            for (int i = 0; i < 4; i++) acc[mi][nf][i] = 0.f;

#define LOAD1(stg, chv) do {                                        \
        uint32_t sb_ = smb + (uint32_t)(stg) * G1_STAGE;            \
        size_t kk_ = kbase + (size_t)(chv) * 64;                    \
        CPA16(sb_ + G1_A + aoff, gA + kk_);                         \
        CPA16(sb_ + G1_A + aoff + 16, gA + kk_ + 8);                \
        CPA16(sb_ + G1_BH + boff0, gB0h + kk_);                     \
        CPA16(sb_ + G1_BH + boff0 + 16, gB0h + kk_ + 8);            \
        CPA16(sb_ + G1_BH + boff1, gB1h + kk_);                     \
        CPA16(sb_ + G1_BH + boff1 + 16, gB1h + kk_ + 8);            \
    } while (0)

    LOAD1(0, 0);
    CPA_COMMIT();
    if (nchk > 1) LOAD1(1, 1);
    CPA_COMMIT();
    if (nchk > 2) LOAD1(2, 2);
    CPA_COMMIT();

    for (int ch = 0; ch < nchk; ch++) {
        CPA_WAIT2();
        __syncthreads();
        if (ch + 3 < nchk) {
            int s2 = ch + 3; while (s2 >= NST1) s2 -= NST1;
            LOAD1(s2, ch + 3);
        }
        CPA_COMMIT();

        int cs = ch; while (cs >= NST1) cs -= NST1;
        const uint32_t sbase = smb + (uint32_t)cs * G1_STAGE;
#pragma unroll
        for (int ks = 0; ks < 4; ks++) {
            const int k2 = ks * 32;
            uint32_t ah[2][4];
#pragma unroll
            for (int mi = 0; mi < 2; mi++) {
                uint32_t aaddr = sbase + G1_A +
                    (uint32_t)(warpM + mi * 16 + (lane & 15)) * ROWB1 + k2 +
                    ((lane >> 4) & 1) * 16;
                LDSM4(ah[mi][0], ah[mi][1], ah[mi][2], ah[mi][3], aaddr);
            }
#pragma unroll
            for (int half = 0; half < 2; half++) {
                uint32_t bh[2][4];
#pragma unroll
                for (int j = 0; j < 2; j++) {
                    int nb = half * 2 + j;
                    uint32_t baddr = sbase + G1_BH +
                        (uint32_t)(warpN + nb * 16 + (lane & 7) + ((lane >> 4) & 1) * 8) * ROWB1 +
                        k2 + ((lane >> 3) & 1) * 16;
                    LDSM4(bh[j][0], bh[j][1], bh[j][2], bh[j][3], baddr);
                }
#pragma unroll
                for (int mi = 0; mi < 2; mi++)
#pragma unroll
                    for (int jf = 0; jf < 4; jf++) {
                        int j = jf >> 1;
                        float* a4 = acc[mi][half * 4 + jf];
                        mma16816(a4, ah[mi], bh[j][(jf & 1) * 2], bh[j][(jf & 1) * 2 + 1]);
                    }
            }
        }
    }
#undef LOAD1

    float* Cp = Cpart + (size_t)z * NROI * FF;
#pragma unroll
    for (int mi = 0; mi < 2; mi++) {
        int mrow = m0 + warpM + mi * 16 + (lane >> 2);
#pragma unroll
        for (int nf = 0; nf < 8; nf++) {
            int n = warpN + nf * 8 + (lane & 3) * 2;
            if (mrow < NROI)
                *(float2*)(Cp + (size_t)mrow * FF + n) =
                    make_float2(acc[mi][nf][0], acc[mi][nf][1]);
            if (mrow + 8 < NROI)
                *(float2*)(Cp + (size_t)(mrow + 8) * FF + n) =
                    make_float2(acc[mi][nf][2], acc[mi][nf][3]);
        }
    }
}

// ---------------- kernel 5b: GEMM2 HMMA (TERMS=3, short-K safe) --------------
__global__ __launch_bounds__(512) void k_hmma3(
    const __half* __restrict__ Ahi, const __half* __restrict__ Alo,
    const __half* __restrict__ Bhi, const __half* __restrict__ Blo,
    float* __restrict__ Cpart, int M, int Kd, int slice, int nchk) {
    constexpr uint32_t AH_OFF = 0;
    constexpr uint32_t AL_OFF = 10240;
    constexpr uint32_t BH_OFF = 20480;
    constexpr uint32_t BL_OFF = 40960;
    constexpr uint32_t STAGE_B = 61440;

    extern __shared__ char sm[];
    const uint32_t smb = smem_u32(sm);
    const int tid = threadIdx.x;
    const int wid = tid >> 5, lane = tid & 31;
    const int m0 = blockIdx.x * 128;
    const size_t kbase = (size_t)blockIdx.z * slice;

    const int warpM = (wid >> 2) * 32;
    const int warpN = (wid & 3) * 64;

    const int lr = tid >> 2;
    const int lch = tid & 3;
    int garow = m0 + lr;
    if (garow >= M) garow = M - 1;
    const __half* gAhi = Ahi + (size_t)garow * Kd + lch * 8;
    const __half* gAlo = Alo + (size_t)garow * Kd + lch * 8;
    const __half* gB0hi = Bhi + (size_t)lr * Kd + lch * 8;
    const __half* gB0lo = Blo + (size_t)lr * Kd + lch * 8;
    const __half* gB1hi = Bhi + (size_t)(lr + 128) * Kd + lch * 8;
    const __half* gB1lo = Blo + (size_t)(lr + 128) * Kd + lch * 8;
    const uint32_t aoff = (uint32_t)lr * ROWB + lch * 16;
    const uint32_t boff0 = aoff;
    const uint32_t boff1 = (uint32_t)(lr + 128) * ROWB + lch * 16;

    float acc[2][8][4];
#pragma unroll
    for (int mi = 0; mi < 2; mi++)
#pragma unroll
        for (int nf = 0; nf < 8; nf++)
#pragma unroll
            for (int i = 0; i < 4; i++) acc[mi][nf][i] = 0.f;

#define LOAD_STAGE(stg, chv) do {                                   \
        uint32_t sb_ = smb + (uint32_t)(stg) * STAGE_B;             \
        size_t kk_ = kbase + (size_t)(chv) * 32;                    \
        CPA16(sb_ + AH_OFF + aoff, gAhi + kk_);                     \
        CPA16(sb_ + AL_OFF + aoff, gAlo + kk_);                     \
        CPA16(sb_ + BH_OFF + boff0, gB0hi + kk_);                   \
        CPA16(sb_ + BH_OFF + boff1, gB1hi + kk_);                   \
        CPA16(sb_ + BL_OFF + boff0, gB0lo + kk_);                   \
        CPA16(sb_ + BL_OFF + boff1, gB1lo + kk_);                   \
    } while (0)

    LOAD_STAGE(0, 0);
    CPA_COMMIT();
    if (nchk > 1) LOAD_STAGE(1, 1);
    CPA_COMMIT();

    int stg = 0;
    for (int ch = 0; ch < nchk; ch++) {
        if (ch + 2 < nchk) {
            int s2 = stg + 2; if (s2 >= NSTAGE) s2 -= NSTAGE;
            LOAD_STAGE(s2, ch + 2);
        }
        CPA_COMMIT();
        if (nchk > 2) { CPA_WAIT2(); } else { CPA_WAIT0(); }
        __syncthreads();

        const uint32_t sbase = smb + (uint32_t)stg * STAGE_B;
#pragma unroll
        for (int ks = 0; ks < 2; ks++) {
            const int k2 = ks * 32;
            uint32_t ah[2][4], al[2][4];
#pragma unroll
            for (int mi = 0; mi < 2; mi++) {
                uint32_t aaddr = sbase + AH_OFF +
                    (uint32_t)(warpM + mi * 16 + (lane & 15)) * ROWB + k2 +
                    ((lane >> 4) & 1) * 16;
                LDSM4(ah[mi][0], ah[mi][1], ah[mi][2], ah[mi][3], aaddr);
                LDSM4(al[mi][0], al[mi][1], al[mi][2], al[mi][3], aaddr + (AL_OFF - AH_OFF));
            }
#pragma unroll
            for (int half = 0; half < 2; half++) {
                uint32_t bh[2][4], bl[2][4];
#pragma unroll
                for (int j = 0; j < 2; j++) {
                    int nb = half * 2 + j;
                    uint32_t baddr = sbase + BH_OFF +
                        (uint32_t)(warpN + nb * 16 + (lane & 7) + ((lane >> 4) & 1) * 8) * ROWB +
                        k2 + ((lane >> 3) & 1) * 16;
                    LDSM4(bh[j][0], bh[j][1], bh[j][2], bh[j][3], baddr);
                    LDSM4(bl[j][0], bl[j][1], bl[j][2], bl[j][3], baddr + (BL_OFF - BH_OFF));
                }
#pragma unroll
                for (int mi = 0; mi < 2; mi++)
#pragma unroll
                    for (int jf = 0; jf < 4; jf++) {
                        int j = jf >> 1;
                        float* a4 = acc[mi][half * 4 + jf];
                        mma16816(a4, ah[mi], bh[j][(jf & 1) * 2], bh[j][(jf & 1) * 2 + 1]);
                        mma16816(a4, ah[mi], bl[j][(jf & 1) * 2], bl[j][(jf & 1) * 2 + 1]);
                        mma16816(a4, al[mi], bh[j][(jf & 1) * 2], bh[j][(jf & 1) * 2 + 1]);
                    }
            }
        }
        __syncthreads();
        stg++; if (stg >= NSTAGE) stg = 0;
    }
#undef LOAD_STAGE

    float* Cp = Cpart + (size_t)blockIdx.z * M * FF;
#pragma unroll
    for (int mi = 0; mi < 2; mi++) {
        int mrow = m0 + warpM + mi * 16 + (lane >> 2);
#pragma unroll
        for (int nf = 0; nf < 8; nf++) {
            int n = warpN + nf * 8 + (lane & 3) * 2;
            if (mrow < M)
                *(float2*)(Cp + (size_t)mrow * FF + n) =
                    make_float2(acc[mi][nf][0], acc[mi][nf][1]);
            if (mrow + 8 < M)
                *(float2*)(Cp + (size_t)(mrow + 8) * FF + n) =
                    make_float2(acc[mi][nf][2], acc[mi][nf][3]);
        }
    }
}

// ---------------- kernel 6: reduce partials + bias + relu -> fp16 hi/lo ------
__global__ void k_reduce_hf(const float* __restrict__ part, const float* __restrict__ bias) {
    int m = blockIdx.x, n = threadIdx.x;
    float s = bias[n];
#pragma unroll
    for (int z = 0; z < KSP; z++) s += part[(size_t)z * NROI * FF + (size_t)m * FF + n];
    float h = fmaxf(s, 0.f);
    __half hi = __float2half_rn(h);
    __half lo = __float2half_rn(h - __half2float(hi));
    g_h1hi[(size_t)m * FF + n] = hi;
    g_h1lo[(size_t)m * FF + n] = lo;
}

// ---------------- kernel 7: fused reduce2 + bias + relu + heads --------------
__global__ void k_tail(const float* __restrict__ part, const float* __restrict__ bias,
                       const float* __restrict__ wcls, const float* __restrict__ bcls,
                       const float* __restrict__ wreg, const float* __restrict__ breg,
                       float* __restrict__ out) {
    __shared__ float h[FF];
    int row = blockIdx.x, tid = threadIdx.x;
    int wid = tid >> 5, lane = tid & 31;
    {
        float s = bias[tid];
#pragma unroll
        for (int z = 0; z < KSP2; z++) s += part[(size_t)z * NROI * FF + (size_t)row * FF + tid];
        h[tid] = fmaxf(s, 0.f);
    }
    __syncthreads();
    if (wid < 6) {
        const float* W = (wid < 2) ? wcls : wreg;
        int ncol = (wid < 2) ? 2 : 4;
        int col = (wid < 2) ? wid : (wid - 2);
        float s = 0.f;
#pragma unroll
        for (int i = 0; i < 8; i++) {
            int n = lane + 32 * i;
            s += h[n] * W[n * ncol + col];
        }
#pragma unroll
        for (int off = 16; off > 0; off >>= 1) s += __shfl_xor_sync(0xffffffffu, s, off);
        if (lane == 0) {
            if (wid < 2) out[row * 2 + col] = s + bcls[col];
            else out[NROI * 2 + row * 4 + col] = s + breg[col];
        }
    }
}

// ---------------------------------------------------------------------------
extern "C" void kernel_launch(void* const* d_in, const int* in_sizes, int n_in,
                              void* d_out, int out_size) {
    const float* features = (const float*)d_in[0];
    const int* rois = (const int*)d_in[1];
    const float* w1 = (const float*)d_in[2];
    const float* b1 = (const float*)d_in[3];
    const float* w2 = (const float*)d_in[4];
    const float* b2 = (const float*)d_in[5];
    const float* w_cls = (const float*)d_in[6];
    const float* b_cls = (const float*)d_in[7];
    const float* w_reg = (const float*)d_in[8];
    const float* b_reg = (const float*)d_in[9];
    float* out = (float*)d_out;

    void* p_Ahf;   cudaGetSymbolAddress(&p_Ahf, g_Ahf);
    void* p_Bhi;   cudaGetSymbolAddress(&p_Bhi, g_Bhi);
    void* p_part1; cudaGetSymbolAddress(&p_part1, g_part1);
    void* p_h1hi;  cudaGetSymbolAddress(&p_h1hi, g_h1hi);
    void* p_h1lo;  cudaGetSymbolAddress(&p_h1lo, g_h1lo);
    void* p_B2hi;  cudaGetSymbolAddress(&p_B2hi, g_B2hi);
    void* p_B2lo;  cudaGetSymbolAddress(&p_B2lo, g_B2lo);
    void* p_part2; cudaGetSymbolAddress(&p_part2, g_part2);

    const int smem1 = NST1 * G1_STAGE;  // 221184
    const int smem2 = NSTAGE * 61440;   // 184320
    cudaFuncSetAttribute(k_hmma1, cudaFuncAttributeMaxDynamicSharedMemorySize, smem1);
    cudaFuncSetAttribute(k_hmma3, cudaFuncAttributeMaxDynamicSharedMemorySize, smem2);

    // 1) integral image: colsum -> segment prefixes -> fused x-scan/y-accumulate
    k_colsum<<<dim3(NSEG, CCH), WW>>>(features);
    k_segprefix<<<dim3(NSEG, CCH / 32), 1024>>>();
    k_iscan<<<dim3(NSEG, CCH / 32), 1024>>>(features);

    // 2) ROI pooling -> fp16 A matrix
    k_pool<<<NROI, CCH>>>(rois);

    // 3) weight prep
    k_prep_w1<<<dim3(POOLP * POOLP, CCH / 32, FF / 32), dim3(32, 8)>>>(w1);
    k_prep_w2<<<dim3(FF / 32, FF / 32), dim3(32, 8)>>>(w2);

    // 4) GEMM1 (1-term, BK=64, 4-stage, split-K=9) + reduce -> h1
    k_hmma1<<<dim3((NROI + 127) / 128, 1, KSP), 512, smem1>>>(
        (const __half*)p_Ahf, (const __half*)p_Bhi, (float*)p_part1);
    k_reduce_hf<<<NROI, FF>>>((const float*)p_part1, b1);

    // 5) GEMM2 (fp16 3-term, split-K=8)
    k_hmma3<<<dim3((NROI + 127) / 128, 1, KSP2), 512, smem2>>>(
        (const __half*)p_h1hi, (const __half*)p_h1lo,
        (const __half*)p_B2hi, (const __half*)p_B2lo,
        (float*)p_part2, NROI, FF, SLICE2, NCHK2);

    // 6) fused reduce + bias + relu + heads
    k_tail<<<NROI, FF>>>((const float*)p_part2, b2, w_cls, b_cls, w_reg, b_reg, out);

    (void)in_sizes; (void)n_in; (void)out_size;
}

// round 17
// speedup vs baseline: 1.1127x; 1.1127x over previous
#include <cuda_runtime.h>
#include <cuda_fp16.h>
#include <cstdint>

// Problem constants
#define CCH 256
#define HH 336
#define WW 336
#define NROI 2000
#define POOLP 7
#define K1 (CCH * POOLP * POOLP)  // 12544
#define FF 256

// ---- GEMM1 (1-term, BK=64, 4-stage, single-barrier, always-commit) ----
#define KSP 9                  // split-K slices for GEMM1 -> 144 CTAs
#define NCH64 (K1 / 64)        // 196 BK-64 chunks total
#define Q64 (NCH64 / KSP)      // 21
#define R64 (NCH64 % KSP)      // 7
#define ROWB1 144              // 128B data + 16B pad
#define G1_A 0
#define G1_BH 18432            // 128*144
#define G1_STAGE 55296         // + 256*144
#define NST1 4
// ---- GEMM2 (BK=32, split-K=8 -> 128 CTAs, nchk=1) ----
#define KSP2 8
#define SLICE2 (FF / KSP2)     // 32
#define NCHK2 (SLICE2 / 32)    // 1
#define ROWB 80
#define NSTAGE 3

// ---------------- static device scratch ----------------
__device__ float g_xscan[(size_t)HH * (WW + 1) * CCH];
__device__ float g_ii[(size_t)(HH + 1) * (WW + 1) * CCH];
__device__ __half g_Ahf[(size_t)NROI * K1];          // pooled A, fp16
__device__ __half g_Bhi[(size_t)FF * K1];            // w1^T fp16  [f][k']
__device__ float g_part1[(size_t)KSP * NROI * FF];
__device__ __half g_h1hi[(size_t)NROI * FF];
__device__ __half g_h1lo[(size_t)NROI * FF];
__device__ __half g_B2hi[(size_t)FF * FF];           // w2^T hi  [f][k]
__device__ __half g_B2lo[(size_t)FF * FF];
__device__ float g_part2[(size_t)KSP2 * NROI * FF];

// ================= helpers =================
__device__ __forceinline__ uint32_t smem_u32(const void* p) {
    uint32_t a;
    asm("{ .reg .u64 t; cvta.to.shared.u64 t, %1; cvt.u32.u64 %0, t; }" : "=r"(a) : "l"(p));
    return a;
}
#define CPA16(sdst, gsrc) \
    asm volatile("cp.async.cg.shared.global [%0], [%1], 16;" \
                 :: "r"(sdst), "l"(__cvta_generic_to_global(gsrc)) : "memory")
#define CPA_COMMIT() asm volatile("cp.async.commit_group;" ::: "memory")
#define CPA_WAIT0()  asm volatile("cp.async.wait_group 0;" ::: "memory")
#define CPA_WAIT2()  asm volatile("cp.async.wait_group 2;" ::: "memory")

#define LDSM4(r0, r1, r2, r3, addr) \
    asm volatile("ldmatrix.sync.aligned.m8n8.x4.shared.b16 {%0,%1,%2,%3}, [%4];" \
                 : "=r"(r0), "=r"(r1), "=r"(r2), "=r"(r3) : "r"(addr))

__device__ __forceinline__ void mma16816(float* c, const uint32_t* a,
                                         uint32_t b0, uint32_t b1) {
    asm volatile(
        "mma.sync.aligned.m16n8k16.row.col.f32.f16.f16.f32 "
        "{%0,%1,%2,%3}, {%4,%5,%6,%7}, {%8,%9}, {%0,%1,%2,%3};"
        : "+f"(c[0]), "+f"(c[1]), "+f"(c[2]), "+f"(c[3])
        : "r"(a[0]), "r"(a[1]), "r"(a[2]), "r"(a[3]), "r"(b0), "r"(b1));
}

// ---------------- kernel 1: x-prefix scan + channel-innermost transpose ------
__global__ void k_xscan(const float* __restrict__ f) {
    __shared__ float s[32][WW + 1];
    int y = blockIdx.x, cg = blockIdx.y;
    int w = threadIdx.x >> 5, lane = threadIdx.x & 31;
    int c = cg * 32 + w;
    const float* row = f + (size_t)c * HH * WW + (size_t)y * WW;
    if (lane == 0) s[w][0] = 0.f;
    float running = 0.f;
#pragma unroll
    for (int chunk = 0; chunk < 11; chunk++) {
        int x = chunk * 32 + lane;
        float v = (x < WW) ? row[x] : 0.f;
#pragma unroll
        for (int off = 1; off < 32; off <<= 1) {
            float t = __shfl_up_sync(0xffffffffu, v, off);
            if (lane >= off) v += t;
        }
        float tot = __shfl_sync(0xffffffffu, v, 31);
        v += running;
        running += tot;
        if (x < WW) s[w][x + 1] = v;
    }
    __syncthreads();
    size_t base = (size_t)y * (WW + 1) * CCH + cg * 32;
    for (int i = threadIdx.x; i < (WW + 1) * 32; i += 1024) {
        int x = i >> 5, cl = i & 31;
        g_xscan[base + (size_t)x * CCH + cl] = s[cl][x];
    }
}

// ---------------- kernel 2: y-prefix sum (float4, 8-deep load batches) -------
__global__ void k_yscan() {
    int idx = blockIdx.x * blockDim.x + threadIdx.x;
    if (idx >= (WW + 1) * (CCH / 4)) return;
    int x = idx / (CCH / 4), c4 = idx % (CCH / 4);
    size_t off = (size_t)x * CCH + (size_t)c4 * 4;
    const size_t rs = (size_t)(WW + 1) * CCH;
    float4 run = make_float4(0.f, 0.f, 0.f, 0.f);
    *(float4*)&g_ii[off] = run;  // y = 0 row
    for (int yb = 0; yb < HH; yb += 8) {
        float4 v[8];
#pragma unroll
        for (int i = 0; i < 8; i++)
            v[i] = *(const float4*)&g_xscan[(size_t)(yb + i) * rs + off];
#pragma unroll
        for (int i = 0; i < 8; i++) {
            run.x += v[i].x; run.y += v[i].y; run.z += v[i].z; run.w += v[i].w;
            *(float4*)&g_ii[(size_t)(yb + i + 1) * rs + off] = run;
        }
    }
}

// ---------------- kernel 3: ROI pool -> fp16 A (one block per roi, bin-row) --
// grid (NROI, POOLP). All 28 corner loads per thread independent -> high MLP.
__global__ void k_pool(const int* __restrict__ rois) {
    int roi = blockIdx.x, py = blockIdx.y, c = threadIdx.x;
    int x1 = rois[roi * 4 + 0], y1 = rois[roi * 4 + 1];
    int x2 = rois[roi * 4 + 2], y2 = rois[roi * 4 + 3];
    int Ly = y2 - y1 + 1, Lx = x2 - x1 + 1;
    const size_t rowstride = (size_t)(WW + 1) * CCH;

    int ylo = y1 + (py * Ly) / POOLP;
    int yhi = y1 + ((py + 1) * Ly + POOLP - 1) / POOLP;
    const float* rlo = g_ii + (size_t)ylo * rowstride + c;
    const float* rhi = g_ii + (size_t)yhi * rowstride + c;
    float invdy = 1.f / (float)(yhi - ylo);
    size_t outbase = (size_t)roi * K1 + (size_t)py * POOLP * CCH + c;

#pragma unroll
    for (int px = 0; px < POOLP; px++) {
        int xlo = x1 + (px * Lx) / POOLP;
        int xhi = x1 + ((px + 1) * Lx + POOLP - 1) / POOLP;
        float s = rhi[(size_t)xhi * CCH] - rlo[(size_t)xhi * CCH]
                - rhi[(size_t)xlo * CCH] + rlo[(size_t)xlo * CCH];
        float v = s * invdy / (float)(xhi - xlo);
        g_Ahf[outbase + (size_t)px * CCH] = __float2half_rn(v);
    }
}

// ---------------- kernel 4: w1 -> transposed fp16 [f][p*256+c] ---------------
__global__ void k_prep_w1(const float* __restrict__ w1) {
    __shared__ float s[32][33];
    int p = blockIdx.x, c0 = blockIdx.y * 32, f0 = blockIdx.z * 32;
    int tx = threadIdx.x, ty = threadIdx.y;
#pragma unroll
    for (int i = 0; i < 4; i++) {
        int cl = ty + i * 8;
        s[cl][tx] = w1[((size_t)(c0 + cl) * (POOLP * POOLP) + p) * FF + f0 + tx];
    }
    __syncthreads();
#pragma unroll
    for (int i = 0; i < 4; i++) {
        int fl = ty + i * 8;
        size_t idx = (size_t)(f0 + fl) * K1 + (size_t)p * CCH + c0 + tx;
        g_Bhi[idx] = __float2half_rn(s[tx][fl]);
    }
}

// ---------------- kernel 4b: w2 -> transposed fp16 hi/lo [f][k] --------------
__global__ void k_prep_w2(const float* __restrict__ w2) {
    __shared__ float s[32][33];
    int k0 = blockIdx.x * 32, f0 = blockIdx.y * 32;
    int tx = threadIdx.x, ty = threadIdx.y;
#pragma unroll
    for (int i = 0; i < 4; i++) {
        int kl = ty + i * 8;
        s[kl][tx] = w2[(size_t)(k0 + kl) * FF + f0 + tx];
    }
    __syncthreads();
#pragma unroll
    for (int i = 0; i < 4; i++) {
        int fl = ty + i * 8;
        float v = s[tx][fl];
        __half hi = __float2half_rn(v);
        __half lo = __float2half_rn(v - __half2float(hi));
        size_t idx = (size_t)(f0 + fl) * FF + k0 + tx;
        g_B2hi[idx] = hi;
        g_B2lo[idx] = lo;
    }
}

// ---------------- kernel 5a: GEMM1 HMMA (1-term, BK=64, 4-stage) -------------
__global__ __launch_bounds__(512) void k_hmma1(
    const __half* __restrict__ A, const __half* __restrict__ Bhi,
    float* __restrict__ Cpart) {
    extern __shared__ char sm[];
    const uint32_t smb = smem_u32(sm);
    const int tid = threadIdx.x;
    const int wid = tid >> 5, lane = tid & 31;
    const int m0 = blockIdx.x * 128;
    const int z = blockIdx.z;
    const int nchk = (z < R64) ? (Q64 + 1) : Q64;
    const int cstart = z * Q64 + min(z, R64);
    const size_t kbase = (size_t)cstart * 64;

    const int warpM = (wid >> 2) * 32;
    const int warpN = (wid & 3) * 64;

    const int lr = tid >> 2;
    const int seg = tid & 3;
    int garow = m0 + lr;
    if (garow >= NROI) garow = NROI - 1;
    const __half* gA = A + (size_t)garow * K1 + seg * 16;
    const __half* gB0h = Bhi + (size_t)lr * K1 + seg * 16;
    const __half* gB1h = Bhi + (size_t)(lr + 128) * K1 + seg * 16;
    const uint32_t aoff = (uint32_t)lr * ROWB1 + seg * 32;
    const uint32_t boff0 = aoff;
    const uint32_t boff1 = (uint32_t)(lr + 128) * ROWB1 + seg * 32;

    float acc[2][8][4];
#pragma unroll
    for (int mi = 0; mi < 2; mi++)
#pragma unroll
        for (int nf = 0; nf < 8; nf++)
#pragma unroll
            for (int i = 0; i < 4; i++) acc[mi][nf][i] = 0.f;

#define LOAD1(stg, chv) do {                                        \
        uint32_t sb_ = smb + (uint32_t)(stg) * G1_STAGE;            \
        size_t kk_ = kbase + (size_t)(chv) * 64;                    \
        CPA16(sb_ + G1_A + aoff, gA + kk_);                         \
        CPA16(sb_ + G1_A + aoff + 16, gA + kk_ + 8);                \
        CPA16(sb_ + G1_BH + boff0, gB0h + kk_);                     \
        CPA16(sb_ + G1_BH + boff0 + 16, gB0h + kk_ + 8);            \
        CPA16(sb_ + G1_BH + boff1, gB1h + kk_);                     \
        CPA16(sb_ + G1_BH + boff1 + 16, gB1h + kk_ + 8);            \
    } while (0)

    LOAD1(0, 0);
    CPA_COMMIT();
    if (nchk > 1) LOAD1(1, 1);
    CPA_COMMIT();
    if (nchk > 2) LOAD1(2, 2);
    CPA_COMMIT();

    for (int ch = 0; ch < nchk; ch++) {
        CPA_WAIT2();
        __syncthreads();
        if (ch + 3 < nchk) {
            int s2 = ch + 3; while (s2 >= NST1) s2 -= NST1;
            LOAD1(s2, ch + 3);
        }
        CPA_COMMIT();

        int cs = ch; while (cs >= NST1) cs -= NST1;
        const uint32_t sbase = smb + (uint32_t)cs * G1_STAGE;
#pragma unroll
        for (int ks = 0; ks < 4; ks++) {
            const int k2 = ks * 32;
            uint32_t ah[2][4];
#pragma unroll
            for (int mi = 0; mi < 2; mi++) {
                uint32_t aaddr = sbase + G1_A +
                    (uint32_t)(warpM + mi * 16 + (lane & 15)) * ROWB1 + k2 +
                    ((lane >> 4) & 1) * 16;
                LDSM4(ah[mi][0], ah[mi][1], ah[mi][2], ah[mi][3], aaddr);
            }
#pragma unroll
            for (int half = 0; half < 2; half++) {
                uint32_t bh[2][4];
#pragma unroll
                for (int j = 0; j < 2; j++) {
                    int nb = half * 2 + j;
                    uint32_t baddr = sbase + G1_BH +
                        (uint32_t)(warpN + nb * 16 + (lane & 7) + ((lane >> 4) & 1) * 8) * ROWB1 +
                        k2 + ((lane >> 3) & 1) * 16;
                    LDSM4(bh[j][0], bh[j][1], bh[j][2], bh[j][3], baddr);
                }
#pragma unroll
                for (int mi = 0; mi < 2; mi++)
#pragma unroll
                    for (int jf = 0; jf < 4; jf++) {
                        int j = jf >> 1;
                        float* a4 = acc[mi][half * 4 + jf];
                        mma16816(a4, ah[mi], bh[j][(jf & 1) * 2], bh[j][(jf & 1) * 2 + 1]);
                    }
            }
        }
    }
#undef LOAD1

    float* Cp = Cpart + (size_t)z * NROI * FF;
#pragma unroll
    for (int mi = 0; mi < 2; mi++) {
        int mrow = m0 + warpM + mi * 16 + (lane >> 2);
#pragma unroll
        for (int nf = 0; nf < 8; nf++) {
            int n = warpN + nf * 8 + (lane & 3) * 2;
            if (mrow < NROI)
                *(float2*)(Cp + (size_t)mrow * FF + n) =
                    make_float2(acc[mi][nf][0], acc[mi][nf][1]);
            if (mrow + 8 < NROI)
                *(float2*)(Cp + (size_t)(mrow + 8) * FF + n) =
                    make_float2(acc[mi][nf][2], acc[mi][nf][3]);
        }
    }
}

// ---------------- kernel 5b: GEMM2 HMMA (TERMS=3, short-K safe) --------------
__global__ __launch_bounds__(512) void k_hmma3(
    const __half* __restrict__ Ahi, const __half* __restrict__ Alo,
    const __half* __restrict__ Bhi, const __half* __restrict__ Blo,
    float* __restrict__ Cpart, int M, int Kd, int slice, int nchk) {
    constexpr uint32_t AH_OFF = 0;
    constexpr uint32_t AL_OFF = 10240;
    constexpr uint32_t BH_OFF = 20480;
    constexpr uint32_t BL_OFF = 40960;
    constexpr uint32_t STAGE_B = 61440;

    extern __shared__ char sm[];
    const uint32_t smb = smem_u32(sm);
    const int tid = threadIdx.x;
    const int wid = tid >> 5, lane = tid & 31;
    const int m0 = blockIdx.x * 128;
    const size_t kbase = (size_t)blockIdx.z * slice;

    const int warpM = (wid >> 2) * 32;
    const int warpN = (wid & 3) * 64;

    const int lr = tid >> 2;
    const int lch = tid & 3;
    int garow = m0 + lr;
    if (garow >= M) garow = M - 1;
    const __half* gAhi = Ahi + (size_t)garow * Kd + lch * 8;
    const __half* gAlo = Alo + (size_t)garow * Kd + lch * 8;
    const __half* gB0hi = Bhi + (size_t)lr * Kd + lch * 8;
    const __half* gB0lo = Blo + (size_t)lr * Kd + lch * 8;
    const __half* gB1hi = Bhi + (size_t)(lr + 128) * Kd + lch * 8;
    const __half* gB1lo = Blo + (size_t)(lr + 128) * Kd + lch * 8;
    const uint32_t aoff = (uint32_t)lr * ROWB + lch * 16;
    const uint32_t boff0 = aoff;
    const uint32_t boff1 = (uint32_t)(lr + 128) * ROWB + lch * 16;

    float acc[2][8][4];
#pragma unroll
    for (int mi = 0; mi < 2; mi++)
#pragma unroll
        for (int nf = 0; nf < 8; nf++)
#pragma unroll
            for (int i = 0; i < 4; i++) acc[mi][nf][i] = 0.f;

#define LOAD_STAGE(stg, chv) do {                                   \
        uint32_t sb_ = smb + (uint32_t)(stg) * STAGE_B;             \
        size_t kk_ = kbase + (size_t)(chv) * 32;                    \
        CPA16(sb_ + AH_OFF + aoff, gAhi + kk_);                     \
        CPA16(sb_ + AL_OFF + aoff, gAlo + kk_);                     \
        CPA16(sb_ + BH_OFF + boff0, gB0hi + kk_);                   \
        CPA16(sb_ + BH_OFF + boff1, gB1hi + kk_);                   \
        CPA16(sb_ + BL_OFF + boff0, gB0lo + kk_);                   \
        CPA16(sb_ + BL_OFF + boff1, gB1lo + kk_);                   \
    } while (0)

    LOAD_STAGE(0, 0);
    CPA_COMMIT();
    if (nchk > 1) LOAD_STAGE(1, 1);
    CPA_COMMIT();

    int stg = 0;
    for (int ch = 0; ch < nchk; ch++) {
        if (ch + 2 < nchk) {
            int s2 = stg + 2; if (s2 >= NSTAGE) s2 -= NSTAGE;
            LOAD_STAGE(s2, ch + 2);
        }
        CPA_COMMIT();
        if (nchk > 2) { CPA_WAIT2(); } else { CPA_WAIT0(); }
        __syncthreads();

        const uint32_t sbase = smb + (uint32_t)stg * STAGE_B;
#pragma unroll
        for (int ks = 0; ks < 2; ks++) {
            const int k2 = ks * 32;
            uint32_t ah[2][4], al[2][4];
#pragma unroll
            for (int mi = 0; mi < 2; mi++) {
                uint32_t aaddr = sbase + AH_OFF +
                    (uint32_t)(warpM + mi * 16 + (lane & 15)) * ROWB + k2 +
                    ((lane >> 4) & 1) * 16;
                LDSM4(ah[mi][0], ah[mi][1], ah[mi][2], ah[mi][3], aaddr);
                LDSM4(al[mi][0], al[mi][1], al[mi][2], al[mi][3], aaddr + (AL_OFF - AH_OFF));
            }
#pragma unroll
            for (int half = 0; half < 2; half++) {
                uint32_t bh[2][4], bl[2][4];
#pragma unroll
                for (int j = 0; j < 2; j++) {
                    int nb = half * 2 + j;
                    uint32_t baddr = sbase + BH_OFF +
                        (uint32_t)(warpN + nb * 16 + (lane & 7) + ((lane >> 4) & 1) * 8) * ROWB +
                        k2 + ((lane >> 3) & 1) * 16;
                    LDSM4(bh[j][0], bh[j][1], bh[j][2], bh[j][3], baddr);
                    LDSM4(bl[j][0], bl[j][1], bl[j][2], bl[j][3], baddr + (BL_OFF - BH_OFF));
                }
#pragma unroll
                for (int mi = 0; mi < 2; mi++)
#pragma unroll
                    for (int jf = 0; jf < 4; jf++) {
                        int j = jf >> 1;
                        float* a4 = acc[mi][half * 4 + jf];
                        mma16816(a4, ah[mi], bh[j][(jf & 1) * 2], bh[j][(jf & 1) * 2 + 1]);
                        mma16816(a4, ah[mi], bl[j][(jf & 1) * 2], bl[j][(jf & 1) * 2 + 1]);
                        mma16816(a4, al[mi], bh[j][(jf & 1) * 2], bh[j][(jf & 1) * 2 + 1]);
                    }
            }
        }
        __syncthreads();
        stg++; if (stg >= NSTAGE) stg = 0;
    }
#undef LOAD_STAGE

    float* Cp = Cpart + (size_t)blockIdx.z * M * FF;
#pragma unroll
    for (int mi = 0; mi < 2; mi++) {
        int mrow = m0 + warpM + mi * 16 + (lane >> 2);
#pragma unroll
        for (int nf = 0; nf < 8; nf++) {
            int n = warpN + nf * 8 + (lane & 3) * 2;
            if (mrow < M)
                *(float2*)(Cp + (size_t)mrow * FF + n) =
                    make_float2(acc[mi][nf][0], acc[mi][nf][1]);
            if (mrow + 8 < M)
                *(float2*)(Cp + (size_t)(mrow + 8) * FF + n) =
                    make_float2(acc[mi][nf][2], acc[mi][nf][3]);
        }
    }
}

// ---------------- kernel 6: reduce partials + bias + relu -> fp16 hi/lo ------
__global__ void k_reduce_hf(const float* __restrict__ part, const float* __restrict__ bias) {
    int m = blockIdx.x, n = threadIdx.x;
    float s = bias[n];
#pragma unroll
    for (int z = 0; z < KSP; z++) s += part[(size_t)z * NROI * FF + (size_t)m * FF + n];
    float h = fmaxf(s, 0.f);
    __half hi = __float2half_rn(h);
    __half lo = __float2half_rn(h - __half2float(hi));
    g_h1hi[(size_t)m * FF + n] = hi;
    g_h1lo[(size_t)m * FF + n] = lo;
}

// ---------------- kernel 7: fused reduce2 + bias + relu + heads --------------
__global__ void k_tail(const float* __restrict__ part, const float* __restrict__ bias,
                       const float* __restrict__ wcls, const float* __restrict__ bcls,
                       const float* __restrict__ wreg, const float* __restrict__ breg,
                       float* __restrict__ out) {
    __shared__ float h[FF];
    int row = blockIdx.x, tid = threadIdx.x;
    int wid = tid >> 5, lane = tid & 31;
    {
        float s = bias[tid];
#pragma unroll
        for (int z = 0; z < KSP2; z++) s += part[(size_t)z * NROI * FF + (size_t)row * FF + tid];
        h[tid] = fmaxf(s, 0.f);
    }
    __syncthreads();
    if (wid < 6) {
        const float* W = (wid < 2) ? wcls : wreg;
        int ncol = (wid < 2) ? 2 : 4;
        int col = (wid < 2) ? wid : (wid - 2);
        float s = 0.f;
#pragma unroll
        for (int i = 0; i < 8; i++) {
            int n = lane + 32 * i;
            s += h[n] * W[n * ncol + col];
        }
#pragma unroll
        for (int off = 16; off > 0; off >>= 1) s += __shfl_xor_sync(0xffffffffu, s, off);
        if (lane == 0) {
            if (wid < 2) out[row * 2 + col] = s + bcls[col];
            else out[NROI * 2 + row * 4 + col] = s + breg[col];
        }
    }
}

// ---------------------------------------------------------------------------
extern "C" void kernel_launch(void* const* d_in, const int* in_sizes, int n_in,
                              void* d_out, int out_size) {
    const float* features = (const float*)d_in[0];
    const int* rois = (const int*)d_in[1];
    const float* w1 = (const float*)d_in[2];
    const float* b1 = (const float*)d_in[3];
    const float* w2 = (const float*)d_in[4];
    const float* b2 = (const float*)d_in[5];
    const float* w_cls = (const float*)d_in[6];
    const float* b_cls = (const float*)d_in[7];
    const float* w_reg = (const float*)d_in[8];
    const float* b_reg = (const float*)d_in[9];
    float* out = (float*)d_out;

    void* p_Ahf;   cudaGetSymbolAddress(&p_Ahf, g_Ahf);
    void* p_Bhi;   cudaGetSymbolAddress(&p_Bhi, g_Bhi);
    void* p_part1; cudaGetSymbolAddress(&p_part1, g_part1);
    void* p_h1hi;  cudaGetSymbolAddress(&p_h1hi, g_h1hi);
    void* p_h1lo;  cudaGetSymbolAddress(&p_h1lo, g_h1lo);
    void* p_B2hi;  cudaGetSymbolAddress(&p_B2hi, g_B2hi);
    void* p_B2lo;  cudaGetSymbolAddress(&p_B2lo, g_B2lo);
    void* p_part2; cudaGetSymbolAddress(&p_part2, g_part2);

    const int smem1 = NST1 * G1_STAGE;  // 221184
    const int smem2 = NSTAGE * 61440;   // 184320
    cudaFuncSetAttribute(k_hmma1, cudaFuncAttributeMaxDynamicSharedMemorySize, smem1);
    cudaFuncSetAttribute(k_hmma3, cudaFuncAttributeMaxDynamicSharedMemorySize, smem2);

    // 1) integral image (R14-proven two-pass version)
    k_xscan<<<dim3(HH, CCH / 32), 1024>>>(features);
    k_yscan<<<((WW + 1) * (CCH / 4) + 255) / 256, 256>>>();

    // 2) ROI pooling -> fp16 A (one block per roi x bin-row; 14000 blocks)
    k_pool<<<dim3(NROI, POOLP), CCH>>>(rois);

    // 3) weight prep
    k_prep_w1<<<dim3(POOLP * POOLP, CCH / 32, FF / 32), dim3(32, 8)>>>(w1);
    k_prep_w2<<<dim3(FF / 32, FF / 32), dim3(32, 8)>>>(w2);

    // 4) GEMM1 (1-term, BK=64, 4-stage, split-K=9) + reduce -> h1
    k_hmma1<<<dim3((NROI + 127) / 128, 1, KSP), 512, smem1>>>(
        (const __half*)p_Ahf, (const __half*)p_Bhi, (float*)p_part1);
    k_reduce_hf<<<NROI, FF>>>((const float*)p_part1, b1);

    // 5) GEMM2 (fp16 3-term, split-K=8)
    k_hmma3<<<dim3((NROI + 127) / 128, 1, KSP2), 512, smem2>>>(
        (const __half*)p_h1hi, (const __half*)p_h1lo,
        (const __half*)p_B2hi, (const __half*)p_B2lo,
        (float*)p_part2, NROI, FF, SLICE2, NCHK2);

    // 6) fused reduce + bias + relu + heads
    k_tail<<<NROI, FF>>>((const float*)p_part2, b2, w_cls, b_cls, w_reg, b_reg, out);

    (void)in_sizes; (void)n_in; (void)out_size;
}